// round 16
// baseline (speedup 1.0000x reference)
#include <cuda_runtime.h>
#include <cuda_fp16.h>
#include <cstdint>
#include <math.h>

#define B_  256
#define T_  128
#define X_  256
#define H_  1024

#define BN  64
#define BK  128
#define NSTG 4
#define ALD (BK + 8)                  // 136 halves
#define BLD (BN + 8)                  // 72 halves
#define BST (BK * BLD)                // 9216 halves
#define AST (32 * ALD)                // 4352 halves (TBM=32 everywhere)
#define SH  (AST + BST)               // 13568 halves per stage
#define DYN_PAD 120832                // pad 108544 -> force 1 CTA/SM

#define NBLK 128

// ---------------- device scratch ----------------
__device__ __half g_yh  [B_ * X_];
__device__ float  g_h0f [B_ * H_];
__device__ __half g_a   [B_ * H_];
__device__ __half g_b1  [B_ * H_];
__device__ __half g_b2  [B_ * H_];
__device__ __half g_b3h [(T_ - 1) * B_ * H_];   // z_t history (66 MB)
__device__ float  g_F   [(T_ - 1) * B_ * X_];   // f GEMM results (33 MB)
__device__ float  g_bcomb[H_];

__device__ unsigned g_cnt;
__device__ unsigned g_gen;

#define WH_IN    0
#define WH_H     (256 * 1024)
#define WH_OUTA  (WH_H + 3 * 1024 * 1024)
#define WH_COMBO (WH_OUTA + 1024 * 256)
#define WH_TOT   (WH_COMBO + 1024 * 1024)
__device__ __half g_wh[WH_TOT];

#define CP16(dst, src) \
    asm volatile("cp.async.cg.shared.global [%0], [%1], 16;" :: "r"(dst), "l"(src))
#define CP_COMMIT() asm volatile("cp.async.commit_group;" ::: "memory")
#define CP_WAIT2()  asm volatile("cp.async.wait_group 2;" ::: "memory")

__device__ __forceinline__ float tanhfast(float x) {
    float y;
    asm("tanh.approx.f32 %0, %1;" : "=f"(y) : "f"(x));
    return y;
}
__device__ __forceinline__ void ldsm_x4(uint32_t (&d)[4], uint32_t addr) {
    asm volatile("ldmatrix.sync.aligned.m8n8.x4.shared.b16 {%0,%1,%2,%3}, [%4];"
        : "=r"(d[0]), "=r"(d[1]), "=r"(d[2]), "=r"(d[3]) : "r"(addr));
}
__device__ __forceinline__ void ldsm_x4t(uint32_t (&d)[4], uint32_t addr) {
    asm volatile("ldmatrix.sync.aligned.m8n8.x4.trans.shared.b16 {%0,%1,%2,%3}, [%4];"
        : "=r"(d[0]), "=r"(d[1]), "=r"(d[2]), "=r"(d[3]) : "r"(addr));
}
__device__ __forceinline__ void mma16816(float (&c)[4], const uint32_t (&a)[4],
                                         uint32_t b0, uint32_t b1) {
    asm volatile("mma.sync.aligned.m16n8k16.row.col.f32.f16.f16.f32 "
        "{%0,%1,%2,%3}, {%4,%5,%6,%7}, {%8,%9}, {%0,%1,%2,%3};"
        : "+f"(c[0]), "+f"(c[1]), "+f"(c[2]), "+f"(c[3])
        : "r"(a[0]), "r"(a[1]), "r"(a[2]), "r"(a[3]), "r"(b0), "r"(b1));
}

// ---------------- grid barrier (NBLK co-resident CTAs) ----------------
__device__ __forceinline__ void gbar() {
    __syncthreads();
    if (threadIdx.x == 0) {
        unsigned gen = *(volatile unsigned*)&g_gen;
        __threadfence();
        if (atomicAdd(&g_cnt, 1u) == NBLK - 1) {
            g_cnt = 0;
            __threadfence();
            *(volatile unsigned*)&g_gen = gen + 1;
        } else {
            while (*(volatile unsigned*)&g_gen == gen) { __nanosleep(32); }
            __threadfence();
        }
    }
    __syncthreads();
}

// ---------------- setup kernels ----------------
__global__ void node_init_kernel(const float* __restrict__ x) {
    int i = blockIdx.x * blockDim.x + threadIdx.x;
    if (i == 0) { g_cnt = 0; g_gen = 0; }
    g_yh[i] = __float2half_rn(x[i]);
}

__global__ void cvt_kernel(const float* __restrict__ src, __half* __restrict__ dst, int n) {
    int i = blockIdx.x * blockDim.x + threadIdx.x;
    if (i < n) dst[i] = __float2half_rn(src[i]);
}

__global__ void bcomb_kernel(const float* __restrict__ b_out, const float* __restrict__ W_in,
                             float* __restrict__ bc) {
    int c = blockIdx.x * blockDim.x + threadIdx.x;   // 0..1023
    float s = 0.f;
    for (int k = 0; k < 256; k++) s += b_out[k] * W_in[k * 1024 + c];
    bc[c] = s;
}

// ---------------- core tile GEMM (TBM=32, 8 warps, register epilogue) ----------------
// MODE 0: CoutH = tanh(val + bias)
// MODE 2: CoutH = val (no bias)
// MODE 3: h0f = val + bias; a = tanh
// MODE 4: h0f += dt*(val+bias); a = tanh
// MODE 6: Fout = val (fp32, no bias)
template <int MODE>
__device__ __forceinline__ void tile_gemm(
    const __half* __restrict__ A, const __half* __restrict__ W,
    const float* __restrict__ bias, __half* __restrict__ CoutH,
    float* __restrict__ Fout,
    int K, int N, int ldc,
    float* __restrict__ h0f, __half* __restrict__ aout,
    const float* __restrict__ ts, int t,
    int bm, int bn, bool pref,
    const __half* __restrict__ Wnext, int Nnext)
{
    extern __shared__ __half smem[];
    const int tid  = threadIdx.x;
    const int lane = tid & 31;
    const int w    = tid >> 5;
    const int wm   = w & 1;
    const int wn   = w >> 1;
    const uint32_t sbase = (uint32_t)__cvta_generic_to_shared(smem);

    float cacc[2][4];
    #pragma unroll
    for (int i = 0; i < 2; i++)
        #pragma unroll
        for (int j = 0; j < 4; j++) cacc[i][j] = 0.0f;

    const int NIT = K / BK;

    auto loadAB = [&](int it) {
        if (it < NIT) {
            const int k0 = it * BK;
            uint32_t asb = sbase + (uint32_t)((it % NSTG) * SH) * 2;
            uint32_t bsb = asb + AST * 2;
            #pragma unroll
            for (int i = 0; i < 2; i++) {
                int id = tid + i * 256;
                int r = id >> 4, c8 = id & 15;
                CP16(asb + (uint32_t)(r * ALD + c8 * 8) * 2,
                     A + (size_t)(bm + r) * K + k0 + c8 * 8);
            }
            #pragma unroll
            for (int i = 0; i < 4; i++) {
                int id = tid + i * 256;
                int r = id >> 3, c8 = id & 7;
                CP16(bsb + (uint32_t)(r * BLD + c8 * 8) * 2,
                     W + (size_t)(k0 + r) * N + bn + c8 * 8);
            }
        }
        CP_COMMIT();
    };

    if (pref) {
        // B stages 0..2 already prefetched by caller (previous phase): load A only
        #pragma unroll
        for (int s = 0; s < 3; s++) {
            uint32_t asb = sbase + (uint32_t)(s * SH) * 2;
            #pragma unroll
            for (int i = 0; i < 2; i++) {
                int id = tid + i * 256;
                int r = id >> 4, c8 = id & 15;
                CP16(asb + (uint32_t)(r * ALD + c8 * 8) * 2,
                     A + (size_t)(bm + r) * K + s * BK + c8 * 8);
            }
            CP_COMMIT();
        }
    } else {
        loadAB(0); loadAB(1); loadAB(2);
    }

    const int a_off = (wm * 16 + (lane & 15)) * ALD + (lane >> 4) * 8;
    const int b_off = (lane & 15) * BLD + wn * 16 + (lane >> 4) * 8;

    for (int it = 0; it < NIT; it++) {
        CP_WAIT2();
        __syncthreads();

        uint32_t abase = sbase + (uint32_t)((it % NSTG) * SH) * 2;
        uint32_t arow = abase + (uint32_t)a_off * 2;
        uint32_t brow = abase + AST * 2 + (uint32_t)b_off * 2;

        #pragma unroll
        for (int kf = 0; kf < BK / 16; kf++) {
            uint32_t a[4];
            ldsm_x4(a, arow + kf * 32);
            uint32_t b[4];
            ldsm_x4t(b, brow + (uint32_t)(kf * 16 * BLD) * 2);
            mma16816(cacc[0], a, b[0], b[1]);
            mma16816(cacc[1], a, b[2], b[3]);
        }
        loadAB(it + NSTG - 1);
    }

    // prefetch next phase's B stages 0..2 (weights only, independent of outputs)
    __syncthreads();
    if (Wnext) {
        #pragma unroll
        for (int s = 0; s < 3; s++) {
            uint32_t bsb = sbase + (uint32_t)(s * SH) * 2 + AST * 2;
            #pragma unroll
            for (int i = 0; i < 4; i++) {
                int id = tid + i * 256;
                int r = id >> 3, c8 = id & 7;
                CP16(bsb + (uint32_t)(r * BLD + c8 * 8) * 2,
                     Wnext + (size_t)(s * BK + r) * Nnext + bn + c8 * 8);
            }
            CP_COMMIT();
        }
    }

    // ---- register epilogue (m16n8 layout) ----
    const int r0 = bm + wm * 16 + (lane >> 2);
    const int c2 = (lane & 3) * 2;

    #pragma unroll
    for (int nb = 0; nb < 2; nb++) {
        const int col = bn + wn * 16 + nb * 8 + c2;
        if (MODE == 0) {
            float2 bv = *reinterpret_cast<const float2*>(&bias[col]);
            __half2 p0 = __halves2half2(__float2half_rn(tanhfast(cacc[nb][0] + bv.x)),
                                        __float2half_rn(tanhfast(cacc[nb][1] + bv.y)));
            __half2 p1 = __halves2half2(__float2half_rn(tanhfast(cacc[nb][2] + bv.x)),
                                        __float2half_rn(tanhfast(cacc[nb][3] + bv.y)));
            *reinterpret_cast<__half2*>(&CoutH[(size_t)r0 * ldc + col]) = p0;
            *reinterpret_cast<__half2*>(&CoutH[(size_t)(r0 + 8) * ldc + col]) = p1;
        } else if (MODE == 2) {
            __half2 p0 = __halves2half2(__float2half_rn(cacc[nb][0]),
                                        __float2half_rn(cacc[nb][1]));
            __half2 p1 = __halves2half2(__float2half_rn(cacc[nb][2]),
                                        __float2half_rn(cacc[nb][3]));
            *reinterpret_cast<__half2*>(&CoutH[(size_t)r0 * ldc + col]) = p0;
            *reinterpret_cast<__half2*>(&CoutH[(size_t)(r0 + 8) * ldc + col]) = p1;
        } else if (MODE == 3) {
            float2 bv = *reinterpret_cast<const float2*>(&bias[col]);
            float v00 = cacc[nb][0] + bv.x, v01 = cacc[nb][1] + bv.y;
            float v10 = cacc[nb][2] + bv.x, v11 = cacc[nb][3] + bv.y;
            int hi0 = r0 * ldc + col, hi1 = (r0 + 8) * ldc + col;
            *reinterpret_cast<float2*>(&h0f[hi0]) = make_float2(v00, v01);
            *reinterpret_cast<float2*>(&h0f[hi1]) = make_float2(v10, v11);
            *reinterpret_cast<__half2*>(&aout[hi0]) =
                __halves2half2(__float2half_rn(tanhfast(v00)), __float2half_rn(tanhfast(v01)));
            *reinterpret_cast<__half2*>(&aout[hi1]) =
                __halves2half2(__float2half_rn(tanhfast(v10)), __float2half_rn(tanhfast(v11)));
        } else if (MODE == 4) {
            const float dt = ts[t + 1] - ts[t];
            float2 bv = *reinterpret_cast<const float2*>(&bias[col]);
            int hi0 = r0 * H_ + col, hi1 = (r0 + 8) * H_ + col;
            float2 h0v = *reinterpret_cast<float2*>(&h0f[hi0]);
            float2 h1v = *reinterpret_cast<float2*>(&h0f[hi1]);
            h0v.x += dt * (cacc[nb][0] + bv.x); h0v.y += dt * (cacc[nb][1] + bv.y);
            h1v.x += dt * (cacc[nb][2] + bv.x); h1v.y += dt * (cacc[nb][3] + bv.y);
            *reinterpret_cast<float2*>(&h0f[hi0]) = h0v;
            *reinterpret_cast<float2*>(&h0f[hi1]) = h1v;
            *reinterpret_cast<__half2*>(&aout[hi0]) =
                __halves2half2(__float2half_rn(tanhfast(h0v.x)), __float2half_rn(tanhfast(h0v.y)));
            *reinterpret_cast<__half2*>(&aout[hi1]) =
                __halves2half2(__float2half_rn(tanhfast(h1v.x)), __float2half_rn(tanhfast(h1v.y)));
        } else {  // MODE 6
            *reinterpret_cast<float2*>(&Fout[(size_t)r0 * ldc + col]) =
                make_float2(cacc[nb][0], cacc[nb][1]);
            *reinterpret_cast<float2*>(&Fout[(size_t)(r0 + 8) * ldc + col]) =
                make_float2(cacc[nb][2], cacc[nb][3]);
        }
    }
}

// ---------------- standalone GEMM wrapper ----------------
template <int MODE>
__global__ void __launch_bounds__(256, 1) gemm_k(
    const __half* __restrict__ A, const __half* __restrict__ W,
    const float* __restrict__ bias, __half* __restrict__ CoutH,
    float* __restrict__ Fout,
    int K, int N, int ldc,
    float* __restrict__ h0f, __half* __restrict__ aout,
    const float* __restrict__ ts, int t)
{
    tile_gemm<MODE>(A, W, bias, CoutH, Fout, K, N, ldc, h0f, aout, ts, t,
                    blockIdx.y * 32, blockIdx.x * 64, false, nullptr, 0);
}

// ---------------- one-step kernel: 4 phases, 3 internal barriers ----------------
__global__ void __launch_bounds__(256, 1) node_step(
    const __half* __restrict__ wh, const float* __restrict__ b_h,
    const float* __restrict__ bcomb,
    float* __restrict__ h0f, __half* __restrict__ a,
    __half* __restrict__ b1, __half* __restrict__ b2, __half* __restrict__ b3t,
    const float* __restrict__ ts, int t)
{
    const int bm = (blockIdx.x >> 4) * 32;
    const int bn = (blockIdx.x & 15) * 64;
    const __half* Wh0 = wh + WH_H + 0 * 1024 * 1024;
    const __half* Wh1 = wh + WH_H + 1 * 1024 * 1024;
    const __half* Wh2 = wh + WH_H + 2 * 1024 * 1024;
    const __half* Wc  = wh + WH_COMBO;

    tile_gemm<0>(a, Wh0, b_h + 0 * H_, b1, nullptr, 1024, 1024, 1024,
                 nullptr, nullptr, nullptr, 0, bm, bn, false, Wh1, 1024);
    gbar();
    tile_gemm<0>(b1, Wh1, b_h + 1 * H_, b2, nullptr, 1024, 1024, 1024,
                 nullptr, nullptr, nullptr, 0, bm, bn, true, Wh2, 1024);
    gbar();
    tile_gemm<0>(b2, Wh2, b_h + 2 * H_, b3t, nullptr, 1024, 1024, 1024,
                 nullptr, nullptr, nullptr, 0, bm, bn, true, Wc, 1024);
    gbar();
    tile_gemm<4>(b3t, Wc, bcomb, nullptr, nullptr, 1024, 1024, 0,
                 h0f, a, ts, t, bm, bn, true, nullptr, 0);
}

// ---------------- final scan: out[b,t,:] from F history ----------------
__global__ void scan_kernel(const float* __restrict__ x, const float* __restrict__ F,
                            const float* __restrict__ b_out, const float* __restrict__ ts,
                            float* __restrict__ out)
{
    const int b = blockIdx.x, c = threadIdx.x;
    float y = x[b * X_ + c];
    out[(size_t)b * T_ * X_ + c] = y;
    const float bo = b_out[c];
    for (int t = 0; t < T_ - 1; t++) {
        float dt = ts[t + 1] - ts[t];
        y += dt * (F[((size_t)t * B_ + b) * X_ + c] + bo);
        out[(size_t)b * T_ * X_ + (size_t)(t + 1) * X_ + c] = y;
    }
}

// ---------------- host ----------------
extern "C" void kernel_launch(void* const* d_in, const int* in_sizes, int n_in,
                              void* d_out, int out_size)
{
    const float* x     = (const float*)d_in[0];
    const float* ts    = (const float*)d_in[1];
    const float* W_in  = (const float*)d_in[2];
    const float* b_in  = (const float*)d_in[3];
    const float* W_h   = (const float*)d_in[4];
    const float* b_h   = (const float*)d_in[5];
    const float* W_out = (const float*)d_in[6];
    const float* b_out = (const float*)d_in[7];
    float* out = (float*)d_out;

    float  *ph0f, *pF, *pbcomb;
    __half *pyh, *pa, *pb1, *pb2, *pb3h, *pwh;
    cudaGetSymbolAddress((void**)&pyh,   g_yh);
    cudaGetSymbolAddress((void**)&ph0f,  g_h0f);
    cudaGetSymbolAddress((void**)&pa,    g_a);
    cudaGetSymbolAddress((void**)&pb1,   g_b1);
    cudaGetSymbolAddress((void**)&pb2,   g_b2);
    cudaGetSymbolAddress((void**)&pb3h,  g_b3h);
    cudaGetSymbolAddress((void**)&pF,    g_F);
    cudaGetSymbolAddress((void**)&pbcomb, g_bcomb);
    cudaGetSymbolAddress((void**)&pwh,   g_wh);

    cudaFuncSetAttribute(gemm_k<2>,  cudaFuncAttributeMaxDynamicSharedMemorySize, DYN_PAD);
    cudaFuncSetAttribute(gemm_k<3>,  cudaFuncAttributeMaxDynamicSharedMemorySize, DYN_PAD);
    cudaFuncSetAttribute(gemm_k<6>,  cudaFuncAttributeMaxDynamicSharedMemorySize, DYN_PAD);
    cudaFuncSetAttribute(node_step,  cudaFuncAttributeMaxDynamicSharedMemorySize, DYN_PAD);

    // ---- one-time setup ----
    cvt_kernel<<<(256 * 1024 + 255) / 256, 256>>>(W_in,  pwh + WH_IN,   256 * 1024);
    cvt_kernel<<<(3 * 1024 * 1024 + 255) / 256, 256>>>(W_h, pwh + WH_H, 3 * 1024 * 1024);
    cvt_kernel<<<(1024 * 256 + 255) / 256, 256>>>(W_out, pwh + WH_OUTA, 1024 * 256);
    bcomb_kernel<<<4, 256>>>(b_out, W_in, pbcomb);

    // W_combo = W_out @ W_in : [1024, 1024]
    gemm_k<2><<<dim3(16, 32), 256, DYN_PAD>>>(
        pwh + WH_OUTA, pwh + WH_IN, (const float*)nullptr, pwh + WH_COMBO,
        (float*)nullptr, 256, 1024, 1024,
        (float*)nullptr, (__half*)nullptr, (const float*)nullptr, 0);

    node_init_kernel<<<(B_ * X_) / 256, 256>>>(x);

    // h0f = x @ W_in + b_in ; a = tanh(h0f)
    gemm_k<3><<<dim3(16, 8), 256, DYN_PAD>>>(
        pyh, pwh + WH_IN, b_in, (__half*)nullptr, (float*)nullptr,
        256, 1024, 1024,
        ph0f, pa, (const float*)nullptr, 0);

    // ---- time loop: ONE kernel per step ----
    for (int t = 0; t < T_ - 1; t++) {
        node_step<<<NBLK, 256, DYN_PAD>>>(
            pwh, b_h, pbcomb, ph0f, pa, pb1, pb2,
            pb3h + (size_t)t * B_ * H_, ts, t);
    }

    // ---- deferred output: F = Z_hist @ W_out, then prefix scan ----
    gemm_k<6><<<dim3(4, (T_ - 1) * B_ / 32), 256, DYN_PAD>>>(
        pb3h, pwh + WH_OUTA, (const float*)nullptr, (__half*)nullptr, pF,
        1024, 256, 256,
        (float*)nullptr, (__half*)nullptr, (const float*)nullptr, 0);

    scan_kernel<<<B_, X_>>>(x, pF, b_out, ts, out);
}

// round 17
// speedup vs baseline: 1.0740x; 1.0740x over previous
#include <cuda_runtime.h>
#include <cuda_fp16.h>
#include <cstdint>
#include <math.h>

#define B_  256
#define T_  128
#define X_  256
#define H_  1024

#define BN  64
#define BK  128
#define NSTG 4
#define ALD (BK + 8)                  // 136 halves
#define BLD (BN + 8)                  // 72 halves
#define BST (BK * BLD)                // 9216 halves
#define AST (32 * ALD)                // 4352 halves (TBM=32)
#define SH  (AST + BST)               // halves per stage
#define SM_H (NSTG * SH * 2)          // 108544 bytes

// ---------------- device scratch ----------------
__device__ __half g_yh  [B_ * X_];
__device__ float  g_h0f [B_ * H_];
__device__ __half g_a   [B_ * H_];
__device__ __half g_b1  [B_ * H_];
__device__ __half g_b2  [B_ * H_];
__device__ __half g_b3h [(T_ - 1) * B_ * H_];   // z_t history (66 MB)
__device__ float  g_F   [(T_ - 1) * B_ * X_];   // deferred f results (33 MB)
__device__ float  g_bcomb[H_];

#define WH_IN    0
#define WH_H     (256 * 1024)
#define WH_OUTA  (WH_H + 3 * 1024 * 1024)
#define WH_COMBO (WH_OUTA + 1024 * 256)
#define WH_TOT   (WH_COMBO + 1024 * 1024)
__device__ __half g_wh[WH_TOT];

#define CP16(dst, src) \
    asm volatile("cp.async.cg.shared.global [%0], [%1], 16;" :: "r"(dst), "l"(src))
#define CP_COMMIT() asm volatile("cp.async.commit_group;" ::: "memory")
#define CP_WAIT2()  asm volatile("cp.async.wait_group 2;" ::: "memory")

__device__ __forceinline__ float tanhfast(float x) {
    float y;
    asm("tanh.approx.f32 %0, %1;" : "=f"(y) : "f"(x));
    return y;
}
__device__ __forceinline__ void ldsm_x4(uint32_t (&d)[4], uint32_t addr) {
    asm volatile("ldmatrix.sync.aligned.m8n8.x4.shared.b16 {%0,%1,%2,%3}, [%4];"
        : "=r"(d[0]), "=r"(d[1]), "=r"(d[2]), "=r"(d[3]) : "r"(addr));
}
__device__ __forceinline__ void ldsm_x4t(uint32_t (&d)[4], uint32_t addr) {
    asm volatile("ldmatrix.sync.aligned.m8n8.x4.trans.shared.b16 {%0,%1,%2,%3}, [%4];"
        : "=r"(d[0]), "=r"(d[1]), "=r"(d[2]), "=r"(d[3]) : "r"(addr));
}
__device__ __forceinline__ void mma16816(float (&c)[4], const uint32_t (&a)[4],
                                         uint32_t b0, uint32_t b1) {
    asm volatile("mma.sync.aligned.m16n8k16.row.col.f32.f16.f16.f32 "
        "{%0,%1,%2,%3}, {%4,%5,%6,%7}, {%8,%9}, {%0,%1,%2,%3};"
        : "+f"(c[0]), "+f"(c[1]), "+f"(c[2]), "+f"(c[3])
        : "r"(a[0]), "r"(a[1]), "r"(a[2]), "r"(a[3]), "r"(b0), "r"(b1));
}

// ---------------- setup kernels ----------------
__global__ void node_init_kernel(const float* __restrict__ x) {
    int i = blockIdx.x * blockDim.x + threadIdx.x;
    g_yh[i] = __float2half_rn(x[i]);
}

__global__ void cvt_kernel(const float* __restrict__ src, __half* __restrict__ dst, int n) {
    int i = blockIdx.x * blockDim.x + threadIdx.x;
    if (i < n) dst[i] = __float2half_rn(src[i]);
}

__global__ void bcomb_kernel(const float* __restrict__ b_out, const float* __restrict__ W_in,
                             float* __restrict__ bc) {
    int c = blockIdx.x * blockDim.x + threadIdx.x;   // 0..1023
    float s = 0.f;
    for (int k = 0; k < 256; k++) s += b_out[k] * W_in[k * 1024 + c];
    bc[c] = s;
}

// ---------------- raw-mma fp16 GEMM (TBM=32, 8 warps, register epilogue) ----------------
// MODE 0: CoutH = tanh(val + bias)
// MODE 2: CoutH = val (no bias)
// MODE 3: h0f = val + bias; a = tanh
// MODE 4: h0f += dt*(val+bias); a = tanh   (recurrence)
// MODE 6: Fout = val (fp32, no bias)       (deferred output GEMM)
template <int MODE>
__global__ void __launch_bounds__(256, 1) gemm_k(
    const __half* __restrict__ A, const __half* __restrict__ W,
    const float* __restrict__ bias, __half* __restrict__ CoutH,
    float* __restrict__ Fout,
    int K, int N, int ldc,
    float* __restrict__ h0f, __half* __restrict__ aout,
    const float* __restrict__ ts, int t)
{
    extern __shared__ __half smem[];
    const int tid  = threadIdx.x;
    const int lane = tid & 31;
    const int w    = tid >> 5;
    const int wm   = w & 1;
    const int wn   = w >> 1;
    const int bm   = blockIdx.y * 32;
    const int bn   = blockIdx.x * BN;
    const uint32_t sbase = (uint32_t)__cvta_generic_to_shared(smem);

    float cacc[2][4];
    #pragma unroll
    for (int i = 0; i < 2; i++)
        #pragma unroll
        for (int j = 0; j < 4; j++) cacc[i][j] = 0.0f;

    const int NIT = K / BK;

    auto loadAB = [&](int it) {
        if (it < NIT) {
            const int k0 = it * BK;
            uint32_t asb = sbase + (uint32_t)((it % NSTG) * SH) * 2;
            uint32_t bsb = asb + AST * 2;
            #pragma unroll
            for (int i = 0; i < 2; i++) {
                int id = tid + i * 256;
                int r = id >> 4, c8 = id & 15;
                CP16(asb + (uint32_t)(r * ALD + c8 * 8) * 2,
                     A + (size_t)(bm + r) * K + k0 + c8 * 8);
            }
            #pragma unroll
            for (int i = 0; i < 4; i++) {
                int id = tid + i * 256;
                int r = id >> 3, c8 = id & 7;
                CP16(bsb + (uint32_t)(r * BLD + c8 * 8) * 2,
                     W + (size_t)(k0 + r) * N + bn + c8 * 8);
            }
        }
        CP_COMMIT();
    };

    loadAB(0); loadAB(1); loadAB(2);

    const int a_off = (wm * 16 + (lane & 15)) * ALD + (lane >> 4) * 8;
    const int b_off = (lane & 15) * BLD + wn * 16 + (lane >> 4) * 8;

    for (int it = 0; it < NIT; it++) {
        CP_WAIT2();
        __syncthreads();

        uint32_t abase = sbase + (uint32_t)((it % NSTG) * SH) * 2;
        uint32_t arow = abase + (uint32_t)a_off * 2;
        uint32_t brow = abase + AST * 2 + (uint32_t)b_off * 2;

        #pragma unroll
        for (int kf = 0; kf < BK / 16; kf++) {
            uint32_t a[4];
            ldsm_x4(a, arow + kf * 32);
            uint32_t b[4];
            ldsm_x4t(b, brow + (uint32_t)(kf * 16 * BLD) * 2);
            mma16816(cacc[0], a, b[0], b[1]);
            mma16816(cacc[1], a, b[2], b[3]);
        }
        loadAB(it + NSTG - 1);
    }

    // ---- register epilogue (m16n8 layout) ----
    const int r0 = bm + wm * 16 + (lane >> 2);
    const int c2 = (lane & 3) * 2;

    #pragma unroll
    for (int nb = 0; nb < 2; nb++) {
        const int col = bn + wn * 16 + nb * 8 + c2;
        if (MODE == 0) {
            float2 bv = *reinterpret_cast<const float2*>(&bias[col]);
            __half2 p0 = __halves2half2(__float2half_rn(tanhfast(cacc[nb][0] + bv.x)),
                                        __float2half_rn(tanhfast(cacc[nb][1] + bv.y)));
            __half2 p1 = __halves2half2(__float2half_rn(tanhfast(cacc[nb][2] + bv.x)),
                                        __float2half_rn(tanhfast(cacc[nb][3] + bv.y)));
            *reinterpret_cast<__half2*>(&CoutH[(size_t)r0 * ldc + col]) = p0;
            *reinterpret_cast<__half2*>(&CoutH[(size_t)(r0 + 8) * ldc + col]) = p1;
        } else if (MODE == 2) {
            __half2 p0 = __halves2half2(__float2half_rn(cacc[nb][0]),
                                        __float2half_rn(cacc[nb][1]));
            __half2 p1 = __halves2half2(__float2half_rn(cacc[nb][2]),
                                        __float2half_rn(cacc[nb][3]));
            *reinterpret_cast<__half2*>(&CoutH[(size_t)r0 * ldc + col]) = p0;
            *reinterpret_cast<__half2*>(&CoutH[(size_t)(r0 + 8) * ldc + col]) = p1;
        } else if (MODE == 3) {
            float2 bv = *reinterpret_cast<const float2*>(&bias[col]);
            float v00 = cacc[nb][0] + bv.x, v01 = cacc[nb][1] + bv.y;
            float v10 = cacc[nb][2] + bv.x, v11 = cacc[nb][3] + bv.y;
            int hi0 = r0 * ldc + col, hi1 = (r0 + 8) * ldc + col;
            *reinterpret_cast<float2*>(&h0f[hi0]) = make_float2(v00, v01);
            *reinterpret_cast<float2*>(&h0f[hi1]) = make_float2(v10, v11);
            *reinterpret_cast<__half2*>(&aout[hi0]) =
                __halves2half2(__float2half_rn(tanhfast(v00)), __float2half_rn(tanhfast(v01)));
            *reinterpret_cast<__half2*>(&aout[hi1]) =
                __halves2half2(__float2half_rn(tanhfast(v10)), __float2half_rn(tanhfast(v11)));
        } else if (MODE == 4) {
            const float dt = ts[t + 1] - ts[t];
            float2 bv = *reinterpret_cast<const float2*>(&bias[col]);
            int hi0 = r0 * H_ + col, hi1 = (r0 + 8) * H_ + col;
            float2 h0v = *reinterpret_cast<float2*>(&h0f[hi0]);
            float2 h1v = *reinterpret_cast<float2*>(&h0f[hi1]);
            h0v.x += dt * (cacc[nb][0] + bv.x); h0v.y += dt * (cacc[nb][1] + bv.y);
            h1v.x += dt * (cacc[nb][2] + bv.x); h1v.y += dt * (cacc[nb][3] + bv.y);
            *reinterpret_cast<float2*>(&h0f[hi0]) = h0v;
            *reinterpret_cast<float2*>(&h0f[hi1]) = h1v;
            *reinterpret_cast<__half2*>(&aout[hi0]) =
                __halves2half2(__float2half_rn(tanhfast(h0v.x)), __float2half_rn(tanhfast(h0v.y)));
            *reinterpret_cast<__half2*>(&aout[hi1]) =
                __halves2half2(__float2half_rn(tanhfast(h1v.x)), __float2half_rn(tanhfast(h1v.y)));
        } else {  // MODE 6
            *reinterpret_cast<float2*>(&Fout[(size_t)r0 * ldc + col]) =
                make_float2(cacc[nb][0], cacc[nb][1]);
            *reinterpret_cast<float2*>(&Fout[(size_t)(r0 + 8) * ldc + col]) =
                make_float2(cacc[nb][2], cacc[nb][3]);
        }
    }
}

// ---------------- final scan: out[b, :, :] from F history ----------------
__global__ void scan_kernel(const float* __restrict__ x, const float* __restrict__ F,
                            const float* __restrict__ b_out, const float* __restrict__ ts,
                            float* __restrict__ out)
{
    const int b = blockIdx.x, c = threadIdx.x;
    float y = x[b * X_ + c];
    out[(size_t)b * T_ * X_ + c] = y;
    const float bo = b_out[c];
    for (int t = 0; t < T_ - 1; t++) {
        float dt = ts[t + 1] - ts[t];
        y += dt * (F[((size_t)t * B_ + b) * X_ + c] + bo);
        out[(size_t)b * T_ * X_ + (size_t)(t + 1) * X_ + c] = y;
    }
}

// ---------------- host ----------------
extern "C" void kernel_launch(void* const* d_in, const int* in_sizes, int n_in,
                              void* d_out, int out_size)
{
    const float* x     = (const float*)d_in[0];
    const float* ts    = (const float*)d_in[1];
    const float* W_in  = (const float*)d_in[2];
    const float* b_in  = (const float*)d_in[3];
    const float* W_h   = (const float*)d_in[4];
    const float* b_h   = (const float*)d_in[5];
    const float* W_out = (const float*)d_in[6];
    const float* b_out = (const float*)d_in[7];
    float* out = (float*)d_out;

    float  *ph0f, *pF, *pbcomb;
    __half *pyh, *pa, *pb1, *pb2, *pb3h, *pwh;
    cudaGetSymbolAddress((void**)&pyh,   g_yh);
    cudaGetSymbolAddress((void**)&ph0f,  g_h0f);
    cudaGetSymbolAddress((void**)&pa,    g_a);
    cudaGetSymbolAddress((void**)&pb1,   g_b1);
    cudaGetSymbolAddress((void**)&pb2,   g_b2);
    cudaGetSymbolAddress((void**)&pb3h,  g_b3h);
    cudaGetSymbolAddress((void**)&pF,    g_F);
    cudaGetSymbolAddress((void**)&pbcomb, g_bcomb);
    cudaGetSymbolAddress((void**)&pwh,   g_wh);

    cudaFuncSetAttribute(gemm_k<0>, cudaFuncAttributeMaxDynamicSharedMemorySize, SM_H);
    cudaFuncSetAttribute(gemm_k<2>, cudaFuncAttributeMaxDynamicSharedMemorySize, SM_H);
    cudaFuncSetAttribute(gemm_k<3>, cudaFuncAttributeMaxDynamicSharedMemorySize, SM_H);
    cudaFuncSetAttribute(gemm_k<4>, cudaFuncAttributeMaxDynamicSharedMemorySize, SM_H);
    cudaFuncSetAttribute(gemm_k<6>, cudaFuncAttributeMaxDynamicSharedMemorySize, SM_H);

    // ---- one-time setup ----
    cvt_kernel<<<(256 * 1024 + 255) / 256, 256>>>(W_in,  pwh + WH_IN,   256 * 1024);
    cvt_kernel<<<(3 * 1024 * 1024 + 255) / 256, 256>>>(W_h, pwh + WH_H, 3 * 1024 * 1024);
    cvt_kernel<<<(1024 * 256 + 255) / 256, 256>>>(W_out, pwh + WH_OUTA, 1024 * 256);
    bcomb_kernel<<<4, 256>>>(b_out, W_in, pbcomb);

    // W_combo = W_out @ W_in : [1024, 1024]
    gemm_k<2><<<dim3(16, 32), 256, SM_H>>>(
        pwh + WH_OUTA, pwh + WH_IN, (const float*)nullptr, pwh + WH_COMBO,
        (float*)nullptr, 256, 1024, 1024,
        (float*)nullptr, (__half*)nullptr, (const float*)nullptr, 0);

    node_init_kernel<<<(B_ * X_) / 256, 256>>>(x);

    // h0f = x @ W_in + b_in ; a = tanh(h0f)
    gemm_k<3><<<dim3(16, 8), 256, SM_H>>>(
        pyh, pwh + WH_IN, b_in, (__half*)nullptr, (float*)nullptr,
        256, 1024, 1024,
        ph0f, pa, (const float*)nullptr, 0);

    // ---- time loop: 4 plain launches per step ----
    dim3 blk(256);
    dim3 gridH(16, 8);    // N=1024 -> 128 CTAs

    const __half* Wh = pwh + WH_H;

    for (int t = 0; t < T_ - 1; t++) {
        __half* pb3t = pb3h + (size_t)t * B_ * H_;
        gemm_k<0><<<gridH, blk, SM_H>>>(
            pa,  Wh + 0 * 1024 * 1024, b_h + 0 * H_, pb1, (float*)nullptr,
            1024, 1024, 1024,
            (float*)nullptr, (__half*)nullptr, (const float*)nullptr, 0);
        gemm_k<0><<<gridH, blk, SM_H>>>(
            pb1, Wh + 1 * 1024 * 1024, b_h + 1 * H_, pb2, (float*)nullptr,
            1024, 1024, 1024,
            (float*)nullptr, (__half*)nullptr, (const float*)nullptr, 0);
        gemm_k<0><<<gridH, blk, SM_H>>>(
            pb2, Wh + 2 * 1024 * 1024, b_h + 2 * H_, pb3t, (float*)nullptr,
            1024, 1024, 1024,
            (float*)nullptr, (__half*)nullptr, (const float*)nullptr, 0);
        gemm_k<4><<<gridH, blk, SM_H>>>(
            pb3t, pwh + WH_COMBO, pbcomb, (__half*)nullptr, (float*)nullptr,
            1024, 1024, 0,
            ph0f, pa, ts, t);
    }

    // ---- deferred output: F = Z_hist @ W_out, then prefix scan ----
    gemm_k<6><<<dim3(4, (T_ - 1) * B_ / 32), 256, SM_H>>>(
        pb3h, pwh + WH_OUTA, (const float*)nullptr, (__half*)nullptr, pF,
        1024, 256, 256,
        (float*)nullptr, (__half*)nullptr, (const float*)nullptr, 0);

    scan_kernel<<<B_, X_>>>(x, pF, b_out, ts, out);
}